// round 10
// baseline (speedup 1.0000x reference)
#include <cuda_runtime.h>
#include <cuda_fp16.h>
#include <cstdint>

#define NN 50000
#define NE 800000

// ---------------- static device scratch ----------------
__device__ int    g_cnt[NN];
__device__ int    g_fill[NN];
__device__ int    g_rowptr[NN + 1];
__device__ float  g_invdeg[NN];
__device__ int    g_csr[NE];
__device__ int    g_blksum[64];
__device__ int    g_blkoff[64];
__device__ uint4  g_xh [(size_t)NN * 16];  // x fp16 (128 cols)
__device__ uint4  g_hh0[(size_t)NN * 32];  // layer-0 pre-activations fp16 (256 cols)
__device__ uint4  g_hh1[(size_t)NN * 32];  // layer-1 pre-activations fp16
__device__ uint4  g_mh [(size_t)NN * 32];  // aggregated mean fp16
__device__ float4 g_pre[(size_t)NN * 32];  // layer-2 pre fp32 (128 cols)
__device__ __half g_wh[262144];            // all 6 weights fp16, [D][K]
__device__ float  g_sum[768];              // 3 layers x 256
__device__ float  g_sumsq[768];

#define OFF_WN0 0
#define OFF_WS0 32768
#define OFF_WN1 65536
#define OFF_WS1 131072
#define OFF_WN2 196608
#define OFF_WS2 229376

// ---------------- helpers ----------------
__device__ __forceinline__ void mma_fp16(float* c, const unsigned* a, const unsigned* b) {
    asm("mma.sync.aligned.m16n8k16.row.col.f32.f16.f16.f32 "
        "{%0,%1,%2,%3}, {%4,%5,%6,%7}, {%8,%9}, {%0,%1,%2,%3};"
        : "+f"(c[0]), "+f"(c[1]), "+f"(c[2]), "+f"(c[3])
        : "r"(a[0]), "r"(a[1]), "r"(a[2]), "r"(a[3]),
          "r"(b[0]), "r"(b[1]));
}

// SRC codes: 0 = g_xh (no BN), 1 = g_hh0 (BN layer0), 2 = g_hh1 (BN layer1)
template<int SRC>
__device__ __forceinline__ const uint4* src_ptr() {
    if (SRC == 0) return g_xh;
    if (SRC == 1) return g_hh0;
    return g_hh1;
}

// ---------------- CSR build ----------------
__global__ void k_zero_cnt() {
    int i = blockIdx.x * blockDim.x + threadIdx.x;
    if (i < NN) { g_cnt[i] = 0; g_fill[i] = 0; }
    if (i < 768) { g_sum[i] = 0.f; g_sumsq[i] = 0.f; }
}

__global__ void k_hist(const int* __restrict__ dst) {
    int e = blockIdx.x * blockDim.x + threadIdx.x;
    if (e < NE) atomicAdd(&g_cnt[dst[e]], 1);
}

__global__ void k_scan1() {
    __shared__ int wsum[32];
    const int tid  = threadIdx.x;
    const int lane = tid & 31;
    const int wid  = tid >> 5;
    const int i = blockIdx.x * 1024 + tid;
    int v = (i < NN) ? g_cnt[i] : 0;
    int x = v;
    #pragma unroll
    for (int d = 1; d < 32; d <<= 1) {
        int t = __shfl_up_sync(0xffffffffu, x, d);
        if (lane >= d) x += t;
    }
    if (lane == 31) wsum[wid] = x;
    __syncthreads();
    if (wid == 0) {
        int w = wsum[lane];
        #pragma unroll
        for (int d = 1; d < 32; d <<= 1) {
            int t = __shfl_up_sync(0xffffffffu, w, d);
            if (lane >= d) w += t;
        }
        wsum[lane] = w;
    }
    __syncthreads();
    int incl = x + (wid ? wsum[wid - 1] : 0);
    if (i < NN) {
        g_rowptr[i + 1] = incl;
        g_invdeg[i] = 1.0f / (float)max(v, 1);
    }
    if (tid == 1023) g_blksum[blockIdx.x] = incl;
}

__global__ void k_scan2(int nblk) {
    const int tid = threadIdx.x;           // 64 threads
    int v = (tid < nblk) ? g_blksum[tid] : 0;
    int x = v;
    #pragma unroll
    for (int d = 1; d < 32; d <<= 1) {
        int t = __shfl_up_sync(0xffffffffu, x, d);
        if ((tid & 31) >= d) x += t;
    }
    __shared__ int w0;
    if (tid == 31) w0 = x;
    __syncthreads();
    if (tid < nblk) g_blkoff[tid] = x - v + ((tid >= 32) ? w0 : 0);
    if (tid == 0) g_rowptr[0] = 0;
}

__global__ void k_scan3() {
    const int i = blockIdx.x * 1024 + threadIdx.x;
    if (i < NN) g_rowptr[i + 1] += g_blkoff[blockIdx.x];
}

__global__ void k_fill(const int* __restrict__ src, const int* __restrict__ dst) {
    int e = blockIdx.x * blockDim.x + threadIdx.x;
    if (e < NE) {
        int d = dst[e];
        int p = g_rowptr[d] + atomicAdd(&g_fill[d], 1);
        g_csr[p] = src[e];
    }
}

// ---------------- x -> fp16 convert ----------------
__global__ void k_cvtx(const float* __restrict__ x) {
    const int total = NN * 16;
    int i = blockIdx.x * blockDim.x + threadIdx.x;
    if (i >= total) return;
    const float4* xp = reinterpret_cast<const float4*>(x);
    float4 a = xp[i * 2], b = xp[i * 2 + 1];
    uint4 o;
    __half2* op = (__half2*)&o;
    op[0] = __floats2half2_rn(a.x, a.y);
    op[1] = __floats2half2_rn(a.z, a.w);
    op[2] = __floats2half2_rn(b.x, b.y);
    op[3] = __floats2half2_rn(b.z, b.w);
    g_xh[i] = o;
}

// ---------------- weight transpose + fp16 convert ----------------
__global__ void k_cvtw(const float* __restrict__ w, int K, int D, int off) {
    __shared__ float t[32][33];
    const int d0 = blockIdx.x * 32, k0 = blockIdx.y * 32;
    const int tx = threadIdx.x, ty = threadIdx.y;
    #pragma unroll
    for (int i = ty; i < 32; i += 8)
        t[i][tx] = w[(size_t)(k0 + i) * D + d0 + tx];
    __syncthreads();
    #pragma unroll
    for (int i = ty; i < 32; i += 8)
        g_wh[off + (size_t)(d0 + i) * K + k0 + tx] = __float2half_rn(t[tx][i]);
}

// ---------------- mean aggregation, with deferred BN+ReLU on input ----------------
template<int DIN, int SRC>
__global__ __launch_bounds__(256) void k_agg(
    const float* __restrict__ gamma, const float* __restrict__ beta, int prevLayer)
{
    __shared__ float s_sc[DIN], s_sh[DIN];
    const int tid = threadIdx.x;
    if (SRC != 0) {
        if (tid < DIN) {
            float mu  = g_sum[prevLayer * 256 + tid] * (1.0f / NN);
            float var = g_sumsq[prevLayer * 256 + tid] * (1.0f / NN) - mu * mu;
            float sc  = gamma[tid] * rsqrtf(var + 1e-5f);
            s_sc[tid] = sc;
            s_sh[tid] = beta[tid] - mu * sc;
        }
        __syncthreads();
    }
    const int TPN = DIN / 8;
    int t = blockIdx.x * blockDim.x + tid;
    int node = t / TPN;
    if (node >= NN) return;
    int c8 = t % TPN;
    float sc[8], sh[8];
    if (SRC != 0) {
        #pragma unroll
        for (int j = 0; j < 8; j++) { sc[j] = s_sc[c8 * 8 + j]; sh[j] = s_sh[c8 * 8 + j]; }
    }
    const uint4* __restrict__ hin = src_ptr<SRC>();
    int beg = g_rowptr[node], end = g_rowptr[node + 1];
    float a[8] = {0.f, 0.f, 0.f, 0.f, 0.f, 0.f, 0.f, 0.f};
    for (int e = beg; e < end; e++) {
        int s = g_csr[e];
        uint4 u = hin[(size_t)s * TPN + c8];
        const __half2* hp = (const __half2*)&u;
        #pragma unroll
        for (int j = 0; j < 4; j++) {
            float2 f = __half22float2(hp[j]);
            if (SRC != 0) {
                f.x = fmaxf(f.x * sc[j * 2]     + sh[j * 2],     0.f);
                f.y = fmaxf(f.y * sc[j * 2 + 1] + sh[j * 2 + 1], 0.f);
            }
            a[j * 2]     += f.x;
            a[j * 2 + 1] += f.y;
        }
    }
    float inv = g_invdeg[node];
    uint4 o;
    __half2* op = (__half2*)&o;
    #pragma unroll
    for (int j = 0; j < 4; j++)
        op[j] = __floats2half2_rn(a[j * 2] * inv, a[j * 2 + 1] * inv);
    g_mh[(size_t)node * TPN + c8] = o;
}

// ---------------- fused dual GEMM (fp16 HMMA, 128x64 tile) + BN stats ----------------
// SRC: A2 source + on-the-fly BN of prev layer. DST: 0 -> g_pre fp32, 1 -> g_hh0, 2 -> g_hh1.
template<int K, int DOUT, int SRC, int DST>
__global__ __launch_bounds__(256) void k_gemm(
    int off1, int off2, const float* __restrict__ bias, int layer,
    const float* __restrict__ pgamma, const float* __restrict__ pbeta)
{
    __shared__ unsigned As2[128 * 10];
    __shared__ unsigned Bs2[64 * 10];
    __shared__ float s_sc[K], s_sh[K];

    const int tid    = threadIdx.x;
    const int lane   = tid & 31;
    const int wid    = tid >> 5;
    const int mbase  = (wid >> 1) * 32;
    const int nbase  = (wid & 1) * 32;
    const int n0 = blockIdx.x * 64;
    const int m0 = blockIdx.y * 128;

    if (SRC != 0) {
        if (tid < K) {
            int pl = layer - 1;
            float mu  = g_sum[pl * 256 + tid] * (1.0f / NN);
            float var = g_sumsq[pl * 256 + tid] * (1.0f / NN) - mu * mu;
            float sc  = pgamma[tid] * rsqrtf(var + 1e-5f);
            s_sc[tid] = sc;
            s_sh[tid] = pbeta[tid] - mu * sc;
        }
        __syncthreads();
    }

    const int a_row = tid >> 1;
    const int a_u4  = tid & 1;
    const int b_n   = tid >> 1;
    const int b_u4  = tid & 1;

    const int THK = K / 8;
    const uint4* A1 = g_mh;
    const uint4* A2 = src_ptr<SRC>();
    const __half* B1w = g_wh + off1;
    const __half* B2w = g_wh + off2;

    float acc[2][4][4];
    #pragma unroll
    for (int i = 0; i < 2; i++)
        #pragma unroll
        for (int j = 0; j < 4; j++)
            #pragma unroll
            for (int r = 0; r < 4; r++) acc[i][j][r] = 0.f;

    #pragma unroll
    for (int phase = 0; phase < 2; phase++) {
        const uint4* __restrict__ A = phase ? A2 : A1;
        const __half* __restrict__ B = phase ? B2w : B1w;
        for (int k0 = 0; k0 < K; k0 += 16) {
            {
                const int gr = m0 + a_row;
                uint4 u = (gr < NN) ? A[(size_t)gr * THK + (k0 >> 3) + a_u4]
                                    : make_uint4(0u, 0u, 0u, 0u);
                if (SRC != 0 && phase == 1) {
                    const __half2* hp = (const __half2*)&u;
                    uint4 o2;
                    __half2* op = (__half2*)&o2;
                    #pragma unroll
                    for (int j = 0; j < 4; j++) {
                        float2 f = __half22float2(hp[j]);
                        int kc = k0 + a_u4 * 8 + j * 2;
                        f.x = fmaxf(f.x * s_sc[kc]     + s_sh[kc],     0.f);
                        f.y = fmaxf(f.y * s_sc[kc + 1] + s_sh[kc + 1], 0.f);
                        op[j] = __floats2half2_rn(f.x, f.y);
                    }
                    u = o2;
                }
                unsigned* ap = &As2[a_row * 10 + a_u4 * 4];
                ap[0] = u.x; ap[1] = u.y; ap[2] = u.z; ap[3] = u.w;
            }
            if (b_n < 64) {
                uint4 u = *reinterpret_cast<const uint4*>(
                    B + (size_t)(n0 + b_n) * K + k0 + b_u4 * 8);
                unsigned* bp = &Bs2[b_n * 10 + b_u4 * 4];
                bp[0] = u.x; bp[1] = u.y; bp[2] = u.z; bp[3] = u.w;
            }
            __syncthreads();

            #pragma unroll
            for (int sm = 0; sm < 2; sm++) {
                const int r = mbase + sm * 16 + (lane >> 2);
                unsigned af[4];
                af[0] = As2[r * 10 + (lane & 3)];
                af[1] = As2[(r + 8) * 10 + (lane & 3)];
                af[2] = As2[r * 10 + (lane & 3) + 4];
                af[3] = As2[(r + 8) * 10 + (lane & 3) + 4];
                #pragma unroll
                for (int sn = 0; sn < 4; sn++) {
                    const int cc = nbase + sn * 8 + (lane >> 2);
                    unsigned bf[2];
                    bf[0] = Bs2[cc * 10 + (lane & 3)];
                    bf[1] = Bs2[cc * 10 + (lane & 3) + 4];
                    mma_fp16(acc[sm][sn], af, bf);
                }
            }
            __syncthreads();
        }
    }

    // ---------------- epilogue: bias + store (fp16 or fp32) + BN partials ----------------
    float* Cf = (float*)g_pre;
    __half* Ch = (DST == 1) ? (__half*)g_hh0 : (__half*)g_hh1;

    #pragma unroll
    for (int sn = 0; sn < 4; sn++) {
        const int colg = n0 + nbase + sn * 8 + 2 * (lane & 3);
        const float bb0 = bias[colg];
        const float bb1 = bias[colg + 1];
        float s0 = 0.f, s1 = 0.f, q0 = 0.f, q1 = 0.f;
        #pragma unroll
        for (int sm = 0; sm < 2; sm++) {
            const int r0 = m0 + mbase + sm * 16 + (lane >> 2);
            const int r1 = r0 + 8;
            float v0 = acc[sm][sn][0] + bb0;
            float v1 = acc[sm][sn][1] + bb1;
            float v2 = acc[sm][sn][2] + bb0;
            float v3 = acc[sm][sn][3] + bb1;
            if (r0 < NN) {
                if (DST == 0)
                    *reinterpret_cast<float2*>(Cf + (size_t)r0 * DOUT + colg) =
                        make_float2(v0, v1);
                else
                    *reinterpret_cast<__half2*>(Ch + (size_t)r0 * DOUT + colg) =
                        __floats2half2_rn(v0, v1);
                s0 += v0; q0 += v0 * v0;
                s1 += v1; q1 += v1 * v1;
            }
            if (r1 < NN) {
                if (DST == 0)
                    *reinterpret_cast<float2*>(Cf + (size_t)r1 * DOUT + colg) =
                        make_float2(v2, v3);
                else
                    *reinterpret_cast<__half2*>(Ch + (size_t)r1 * DOUT + colg) =
                        __floats2half2_rn(v2, v3);
                s0 += v2; q0 += v2 * v2;
                s1 += v3; q1 += v3 * v3;
            }
        }
        #pragma unroll
        for (int d = 16; d >= 4; d >>= 1) {
            s0 += __shfl_down_sync(0xffffffffu, s0, d);
            s1 += __shfl_down_sync(0xffffffffu, s1, d);
            q0 += __shfl_down_sync(0xffffffffu, q0, d);
            q1 += __shfl_down_sync(0xffffffffu, q1, d);
        }
        if (lane < 4) {
            const int cg = n0 + nbase + sn * 8 + 2 * lane;
            atomicAdd(&g_sum  [layer * 256 + cg],     s0);
            atomicAdd(&g_sum  [layer * 256 + cg + 1], s1);
            atomicAdd(&g_sumsq[layer * 256 + cg],     q0);
            atomicAdd(&g_sumsq[layer * 256 + cg + 1], q1);
        }
    }
}

// ---------------- final BN apply (layer 2 -> fp32 output) ----------------
__global__ __launch_bounds__(256) void k_bnout(
    const float* __restrict__ gamma, const float* __restrict__ beta,
    float* __restrict__ outp)
{
    __shared__ float s_scale[128], s_shift[128];
    const int tid = threadIdx.x;
    if (tid < 128) {
        float mu  = g_sum[512 + tid] * (1.0f / NN);
        float var = g_sumsq[512 + tid] * (1.0f / NN) - mu * mu;
        float sc  = gamma[tid] * rsqrtf(var + 1e-5f);
        s_scale[tid] = sc;
        s_shift[tid] = beta[tid] - mu * sc;
    }
    __syncthreads();

    const int total = NN * 32;          // float4 groups
    int i = blockIdx.x * blockDim.x + tid;
    if (i >= total) return;
    int c4 = (i & 31) * 4;
    float4 v = g_pre[i];
    v.x = v.x * s_scale[c4 + 0] + s_shift[c4 + 0];
    v.y = v.y * s_scale[c4 + 1] + s_shift[c4 + 1];
    v.z = v.z * s_scale[c4 + 2] + s_shift[c4 + 2];
    v.w = v.w * s_scale[c4 + 3] + s_shift[c4 + 3];
    reinterpret_cast<float4*>(outp)[i] = v;
}

// ---------------- launch ----------------
extern "C" void kernel_launch(void* const* d_in, const int* in_sizes, int n_in,
                              void* d_out, int out_size) {
    const float* x    = (const float*)d_in[0];
    const int*   ei   = (const int*)d_in[1];
    const int*   esrc = ei;
    const int*   edst = ei + NE;
    const float* wn0 = (const float*)d_in[2];
    const float* ws0 = (const float*)d_in[3];
    const float* b0  = (const float*)d_in[4];
    const float* g0  = (const float*)d_in[5];
    const float* be0 = (const float*)d_in[6];
    const float* wn1 = (const float*)d_in[7];
    const float* ws1 = (const float*)d_in[8];
    const float* b1  = (const float*)d_in[9];
    const float* g1  = (const float*)d_in[10];
    const float* be1 = (const float*)d_in[11];
    const float* wn2 = (const float*)d_in[12];
    const float* ws2 = (const float*)d_in[13];
    const float* b2  = (const float*)d_in[14];
    const float* g2  = (const float*)d_in[15];
    const float* be2 = (const float*)d_in[16];
    float* out = (float*)d_out;

    const int NBLK = (NN + 1023) / 1024;   // 49

    k_zero_cnt<<<(NN + 255) / 256, 256>>>();
    k_hist<<<(NE + 255) / 256, 256>>>(edst);
    k_scan1<<<NBLK, 1024>>>();
    k_scan2<<<1, 64>>>(NBLK);
    k_scan3<<<NBLK, 1024>>>();
    k_fill<<<(NE + 255) / 256, 256>>>(esrc, edst);
    k_cvtx<<<(NN * 16 + 255) / 256, 256>>>(x);

    dim3 tb(32, 8);
    k_cvtw<<<dim3(8, 4), tb>>>(wn0, 128, 256, OFF_WN0);
    k_cvtw<<<dim3(8, 4), tb>>>(ws0, 128, 256, OFF_WS0);
    k_cvtw<<<dim3(8, 8), tb>>>(wn1, 256, 256, OFF_WN1);
    k_cvtw<<<dim3(8, 8), tb>>>(ws1, 256, 256, OFF_WS1);
    k_cvtw<<<dim3(4, 8), tb>>>(wn2, 256, 128, OFF_WN2);
    k_cvtw<<<dim3(4, 8), tb>>>(ws2, 256, 128, OFF_WS2);

    const int M_TILES = (NN + 127) / 128;

    // ---- layer 0: x(128) -> pre0(256) fp16 in g_hh0 ----
    k_agg<128, 0><<<(NN * 16 + 255) / 256, 256>>>(nullptr, nullptr, 0);
    k_gemm<128, 256, 0, 1><<<dim3(4, M_TILES), 256>>>(OFF_WN0, OFF_WS0, b0, 0,
                                                      nullptr, nullptr);

    // ---- layer 1: BN0(pre0) -> pre1(256) fp16 in g_hh1 ----
    k_agg<256, 1><<<(NN * 32 + 255) / 256, 256>>>(g0, be0, 0);
    k_gemm<256, 256, 1, 2><<<dim3(4, M_TILES), 256>>>(OFF_WN1, OFF_WS1, b1, 1,
                                                      g0, be0);

    // ---- layer 2: BN1(pre1) -> pre2(128) fp32 in g_pre ----
    k_agg<256, 2><<<(NN * 32 + 255) / 256, 256>>>(g1, be1, 1);
    k_gemm<256, 128, 2, 0><<<dim3(2, M_TILES), 256>>>(OFF_WN2, OFF_WS2, b2, 2,
                                                      g1, be1);

    // ---- final BN -> output ----
    k_bnout<<<(NN * 32 + 255) / 256, 256>>>(g2, be2, out);
}

// round 12
// speedup vs baseline: 1.1572x; 1.1572x over previous
#include <cuda_runtime.h>
#include <cuda_fp16.h>
#include <cstdint>

#define NN 50000
#define NE 800000

// ---------------- static device scratch ----------------
__device__ int    g_cnt[NN];
__device__ int    g_fill[NN];
__device__ int    g_rowptr[NN + 1];
__device__ float  g_invdeg[NN];
__device__ int    g_csr[NE];
__device__ int    g_blksum[64];
__device__ uint4  g_xh[(size_t)NN * 16];   // x fp16 (128 cols)
__device__ uint4  g_hh[(size_t)NN * 32];   // hidden activations fp16
__device__ uint4  g_mh[(size_t)NN * 32];   // aggregated mean fp16
__device__ float4 g_pre[(size_t)NN * 64];  // pre-BN linear output fp32
__device__ __half g_wh[262144];            // all 6 weights fp16, [D][K]
__device__ float  g_sum[768];              // 3 layers x 256
__device__ float  g_sumsq[768];

#define OFF_WN0 0
#define OFF_WS0 32768
#define OFF_WN1 65536
#define OFF_WS1 131072
#define OFF_WN2 196608
#define OFF_WS2 229376

#define ASTRIDE 12   // unsigned units; 48B row stride -> every row 16B aligned

// ---------------- helpers ----------------
__device__ __forceinline__ void mma_fp16(float* c, const unsigned* a, const unsigned* b) {
    asm("mma.sync.aligned.m16n8k16.row.col.f32.f16.f16.f32 "
        "{%0,%1,%2,%3}, {%4,%5,%6,%7}, {%8,%9}, {%0,%1,%2,%3};"
        : "+f"(c[0]), "+f"(c[1]), "+f"(c[2]), "+f"(c[3])
        : "r"(a[0]), "r"(a[1]), "r"(a[2]), "r"(a[3]),
          "r"(b[0]), "r"(b[1]));
}
__device__ __forceinline__ void ldsm_x4(unsigned* r, uint32_t addr) {
    asm volatile("ldmatrix.sync.aligned.m8n8.x4.shared.b16 {%0,%1,%2,%3}, [%4];"
        : "=r"(r[0]), "=r"(r[1]), "=r"(r[2]), "=r"(r[3]) : "r"(addr));
}
__device__ __forceinline__ void ldsm_x2(unsigned* r, uint32_t addr) {
    asm volatile("ldmatrix.sync.aligned.m8n8.x2.shared.b16 {%0,%1}, [%2];"
        : "=r"(r[0]), "=r"(r[1]) : "r"(addr));
}

// ---------------- CSR build ----------------
__global__ void k_zero_cnt() {
    int i = blockIdx.x * blockDim.x + threadIdx.x;
    if (i < NN) { g_cnt[i] = 0; g_fill[i] = 0; }
    if (i < 768) { g_sum[i] = 0.f; g_sumsq[i] = 0.f; }
}

__global__ void k_hist(const int* __restrict__ dst) {
    int e = blockIdx.x * blockDim.x + threadIdx.x;
    if (e < NE) atomicAdd(&g_cnt[dst[e]], 1);
}

__global__ void k_scan1() {
    __shared__ int wsum[32];
    const int tid  = threadIdx.x;
    const int lane = tid & 31;
    const int wid  = tid >> 5;
    const int i = blockIdx.x * 1024 + tid;
    int v = (i < NN) ? g_cnt[i] : 0;
    int x = v;
    #pragma unroll
    for (int d = 1; d < 32; d <<= 1) {
        int t = __shfl_up_sync(0xffffffffu, x, d);
        if (lane >= d) x += t;
    }
    if (lane == 31) wsum[wid] = x;
    __syncthreads();
    if (wid == 0) {
        int w = wsum[lane];
        #pragma unroll
        for (int d = 1; d < 32; d <<= 1) {
            int t = __shfl_up_sync(0xffffffffu, w, d);
            if (lane >= d) w += t;
        }
        wsum[lane] = w;
    }
    __syncthreads();
    int incl = x + (wid ? wsum[wid - 1] : 0);
    if (i < NN) {
        g_rowptr[i + 1] = incl;
        g_invdeg[i] = 1.0f / (float)max(v, 1);
    }
    if (tid == 1023) g_blksum[blockIdx.x] = incl;
}

__global__ void k_scan23() {
    __shared__ int sv[64];
    const int tid = threadIdx.x;
    const int bid = blockIdx.x;
    if (tid < 64) sv[tid] = (tid < bid) ? g_blksum[tid] : 0;
    __syncthreads();
    if (tid < 32) {
        int v = sv[tid] + sv[tid + 32];
        #pragma unroll
        for (int d = 16; d; d >>= 1) v += __shfl_down_sync(0xffffffffu, v, d);
        if (tid == 0) sv[0] = v;
    }
    __syncthreads();
    const int off = sv[0];
    const int i = bid * 1024 + tid;
    if (i < NN) g_rowptr[i + 1] += off;
    if (i == 0) g_rowptr[0] = 0;
}

__global__ void k_fill(const int* __restrict__ src, const int* __restrict__ dst) {
    int e = blockIdx.x * blockDim.x + threadIdx.x;
    if (e < NE) {
        int d = dst[e];
        int p = g_rowptr[d] + atomicAdd(&g_fill[d], 1);
        g_csr[p] = src[e];
    }
}

// ---------------- x -> fp16 convert ----------------
__global__ void k_cvtx(const float* __restrict__ x) {
    const int total = NN * 16;
    int i = blockIdx.x * blockDim.x + threadIdx.x;
    if (i >= total) return;
    const float4* xp = reinterpret_cast<const float4*>(x);
    float4 a = xp[i * 2], b = xp[i * 2 + 1];
    uint4 o;
    __half2* op = (__half2*)&o;
    op[0] = __floats2half2_rn(a.x, a.y);
    op[1] = __floats2half2_rn(a.z, a.w);
    op[2] = __floats2half2_rn(b.x, b.y);
    op[3] = __floats2half2_rn(b.z, b.w);
    g_xh[i] = o;
}

// ---------------- all 6 weight transposes in one launch ----------------
__global__ void k_cvtw_all(const float* __restrict__ w0, const float* __restrict__ w1,
                           const float* __restrict__ w2, const float* __restrict__ w3,
                           const float* __restrict__ w4, const float* __restrict__ w5) {
    __shared__ float t[32][33];
    const int wi = blockIdx.z;
    const float* w; int K, D, off;
    switch (wi) {
        case 0:  w = w0; K = 128; D = 256; off = OFF_WN0; break;
        case 1:  w = w1; K = 128; D = 256; off = OFF_WS0; break;
        case 2:  w = w2; K = 256; D = 256; off = OFF_WN1; break;
        case 3:  w = w3; K = 256; D = 256; off = OFF_WS1; break;
        case 4:  w = w4; K = 256; D = 128; off = OFF_WN2; break;
        default: w = w5; K = 256; D = 128; off = OFF_WS2; break;
    }
    const int d0 = blockIdx.x * 32, k0 = blockIdx.y * 32;
    if (d0 >= D || k0 >= K) return;
    const int tx = threadIdx.x, ty = threadIdx.y;
    #pragma unroll
    for (int i = ty; i < 32; i += 8)
        t[i][tx] = w[(size_t)(k0 + i) * D + d0 + tx];
    __syncthreads();
    #pragma unroll
    for (int i = ty; i < 32; i += 8)
        g_wh[off + (size_t)(d0 + i) * K + k0 + tx] = __float2half_rn(t[tx][i]);
}

// ---------------- mean aggregation ----------------
template<int DIN, bool FROMX>
__global__ void k_agg() {
    const int TPN = DIN / 8;
    int t = blockIdx.x * blockDim.x + threadIdx.x;
    int node = t / TPN;
    if (node >= NN) return;
    int c8 = t % TPN;
    const uint4* __restrict__ hin = FROMX ? g_xh : g_hh;
    int beg = g_rowptr[node], end = g_rowptr[node + 1];
    float a0 = 0.f, a1 = 0.f, a2 = 0.f, a3 = 0.f;
    float a4 = 0.f, a5 = 0.f, a6 = 0.f, a7 = 0.f;
    for (int e = beg; e < end; e++) {
        int s = g_csr[e];
        uint4 u = hin[(size_t)s * TPN + c8];
        const __half2* hp = (const __half2*)&u;
        float2 f0 = __half22float2(hp[0]);
        float2 f1 = __half22float2(hp[1]);
        float2 f2 = __half22float2(hp[2]);
        float2 f3 = __half22float2(hp[3]);
        a0 += f0.x; a1 += f0.y; a2 += f1.x; a3 += f1.y;
        a4 += f2.x; a5 += f2.y; a6 += f3.x; a7 += f3.y;
    }
    float inv = g_invdeg[node];
    uint4 o;
    __half2* op = (__half2*)&o;
    op[0] = __floats2half2_rn(a0 * inv, a1 * inv);
    op[1] = __floats2half2_rn(a2 * inv, a3 * inv);
    op[2] = __floats2half2_rn(a4 * inv, a5 * inv);
    op[3] = __floats2half2_rn(a6 * inv, a7 * inv);
    g_mh[(size_t)node * TPN + c8] = o;
}

// ---------------- fused dual GEMM (fp16 HMMA, 128x64 tile, ldmatrix) ----------------
template<int K, int DOUT, bool FROMX>
__global__ __launch_bounds__(256) void k_gemm(
    int off1, int off2, const float* __restrict__ bias, int layer)
{
    __shared__ unsigned As2[128 * ASTRIDE];   // half2 [m][k-pair], 48B row stride
    __shared__ unsigned Bs2[64 * ASTRIDE];    // half2 [n][k-pair]

    const int tid    = threadIdx.x;
    const int lane   = tid & 31;
    const int wid    = tid >> 5;
    const int mbase  = (wid >> 1) * 32;
    const int nbase  = (wid & 1) * 32;
    const int n0 = blockIdx.x * 64;
    const int m0 = blockIdx.y * 128;

    const int a_row = tid >> 1;
    const int a_u4  = tid & 1;
    const int b_n   = tid >> 1;
    const int b_u4  = tid & 1;

    const int THK = K / 8;
    const uint4* A1 = g_mh;
    const uint4* A2 = FROMX ? g_xh : g_hh;
    const __half* B1w = g_wh + off1;
    const __half* B2w = g_wh + off2;
    float*       C  = (float*)g_pre;

    // ldmatrix source addresses (invariant across chunks: single buffer)
    const uint32_t sbA = (uint32_t)__cvta_generic_to_shared(As2);
    const uint32_t sbB = (uint32_t)__cvta_generic_to_shared(Bs2);
    const int quad = lane >> 3, lr = lane & 7;
    uint32_t addrA[2], addrB[4];
    #pragma unroll
    for (int sm = 0; sm < 2; sm++) {
        int row = mbase + sm * 16 + (quad & 1) * 8 + lr;
        int kp  = (quad >> 1) * 4;
        addrA[sm] = sbA + 4u * (row * ASTRIDE + kp);
    }
    {
        const int l16 = lane & 15;
        #pragma unroll
        for (int sn = 0; sn < 4; sn++) {
            int row = nbase + sn * 8 + (l16 & 7);
            int kp  = (l16 >> 3) * 4;
            addrB[sn] = sbB + 4u * (row * ASTRIDE + kp);
        }
    }

    float acc[2][4][4];
    #pragma unroll
    for (int i = 0; i < 2; i++)
        #pragma unroll
        for (int j = 0; j < 4; j++)
            #pragma unroll
            for (int r = 0; r < 4; r++) acc[i][j][r] = 0.f;

    #pragma unroll
    for (int phase = 0; phase < 2; phase++) {
        const uint4* __restrict__ A = phase ? A2 : A1;
        const __half* __restrict__ B = phase ? B2w : B1w;
        for (int k0 = 0; k0 < K; k0 += 16) {
            {
                const int gr = m0 + a_row;
                uint4 u = (gr < NN) ? A[(size_t)gr * THK + (k0 >> 3) + a_u4]
                                    : make_uint4(0u, 0u, 0u, 0u);
                unsigned* ap = &As2[a_row * ASTRIDE + a_u4 * 4];
                ap[0] = u.x; ap[1] = u.y; ap[2] = u.z; ap[3] = u.w;
            }
            if (b_n < 64) {
                uint4 u = *reinterpret_cast<const uint4*>(
                    B + (size_t)(n0 + b_n) * K + k0 + b_u4 * 8);
                unsigned* bp = &Bs2[b_n * ASTRIDE + b_u4 * 4];
                bp[0] = u.x; bp[1] = u.y; bp[2] = u.z; bp[3] = u.w;
            }
            __syncthreads();

            unsigned af[2][4];
            ldsm_x4(af[0], addrA[0]);
            ldsm_x4(af[1], addrA[1]);
            #pragma unroll
            for (int sn = 0; sn < 4; sn++) {
                unsigned bf[2];
                ldsm_x2(bf, addrB[sn]);
                mma_fp16(acc[0][sn], af[0], bf);
                mma_fp16(acc[1][sn], af[1], bf);
            }
            __syncthreads();
        }
    }

    #pragma unroll
    for (int sn = 0; sn < 4; sn++) {
        const int colg = n0 + nbase + sn * 8 + 2 * (lane & 3);
        const float bb0 = bias[colg];
        const float bb1 = bias[colg + 1];
        float s0 = 0.f, s1 = 0.f, q0 = 0.f, q1 = 0.f;
        #pragma unroll
        for (int sm = 0; sm < 2; sm++) {
            const int r0 = m0 + mbase + sm * 16 + (lane >> 2);
            const int r1 = r0 + 8;
            float v0 = acc[sm][sn][0] + bb0;
            float v1 = acc[sm][sn][1] + bb1;
            float v2 = acc[sm][sn][2] + bb0;
            float v3 = acc[sm][sn][3] + bb1;
            if (r0 < NN) {
                *reinterpret_cast<float2*>(C + (size_t)r0 * DOUT + colg) =
                    make_float2(v0, v1);
                s0 += v0; q0 += v0 * v0;
                s1 += v1; q1 += v1 * v1;
            }
            if (r1 < NN) {
                *reinterpret_cast<float2*>(C + (size_t)r1 * DOUT + colg) =
                    make_float2(v2, v3);
                s0 += v2; q0 += v2 * v2;
                s1 += v3; q1 += v3 * v3;
            }
        }
        #pragma unroll
        for (int d = 16; d >= 4; d >>= 1) {
            s0 += __shfl_down_sync(0xffffffffu, s0, d);
            s1 += __shfl_down_sync(0xffffffffu, s1, d);
            q0 += __shfl_down_sync(0xffffffffu, q0, d);
            q1 += __shfl_down_sync(0xffffffffu, q1, d);
        }
        if (lane < 4) {
            const int cg = n0 + nbase + sn * 8 + 2 * lane;
            atomicAdd(&g_sum  [layer * 256 + cg],     s0);
            atomicAdd(&g_sum  [layer * 256 + cg + 1], s1);
            atomicAdd(&g_sumsq[layer * 256 + cg],     q0);
            atomicAdd(&g_sumsq[layer * 256 + cg + 1], q1);
        }
    }
}

// ---------------- BN finalize (in-block) + apply ----------------
template<int DOUT, bool RELU, bool TOOUT>
__global__ __launch_bounds__(256) void k_bnapply(
    const float* __restrict__ gamma, const float* __restrict__ beta,
    int layer, float* __restrict__ outp)
{
    __shared__ float s_scale[DOUT], s_shift[DOUT];
    const int tid = threadIdx.x;
    if (tid < DOUT) {
        float mu  = g_sum[layer * 256 + tid] * (1.0f / NN);
        float var = g_sumsq[layer * 256 + tid] * (1.0f / NN) - mu * mu;
        float sc  = gamma[tid] * rsqrtf(var + 1e-5f);
        s_scale[tid] = sc;
        s_shift[tid] = beta[tid] - mu * sc;
    }
    __syncthreads();

    const int total = NN * (DOUT / 8);
    int i = blockIdx.x * blockDim.x + tid;
    if (i >= total) return;
    int c8 = (i % (DOUT / 8)) * 8;
    float4 v0 = g_pre[i * 2];
    float4 v1 = g_pre[i * 2 + 1];
    float r0 = v0.x * s_scale[c8 + 0] + s_shift[c8 + 0];
    float r1 = v0.y * s_scale[c8 + 1] + s_shift[c8 + 1];
    float r2 = v0.z * s_scale[c8 + 2] + s_shift[c8 + 2];
    float r3 = v0.w * s_scale[c8 + 3] + s_shift[c8 + 3];
    float r4 = v1.x * s_scale[c8 + 4] + s_shift[c8 + 4];
    float r5 = v1.y * s_scale[c8 + 5] + s_shift[c8 + 5];
    float r6 = v1.z * s_scale[c8 + 6] + s_shift[c8 + 6];
    float r7 = v1.w * s_scale[c8 + 7] + s_shift[c8 + 7];
    if (RELU) {
        r0 = fmaxf(r0, 0.f); r1 = fmaxf(r1, 0.f);
        r2 = fmaxf(r2, 0.f); r3 = fmaxf(r3, 0.f);
        r4 = fmaxf(r4, 0.f); r5 = fmaxf(r5, 0.f);
        r6 = fmaxf(r6, 0.f); r7 = fmaxf(r7, 0.f);
    }
    if (TOOUT) {
        float4* op = reinterpret_cast<float4*>(outp);
        op[i * 2]     = make_float4(r0, r1, r2, r3);
        op[i * 2 + 1] = make_float4(r4, r5, r6, r7);
    } else {
        uint4 o;
        __half2* hp = (__half2*)&o;
        hp[0] = __floats2half2_rn(r0, r1);
        hp[1] = __floats2half2_rn(r2, r3);
        hp[2] = __floats2half2_rn(r4, r5);
        hp[3] = __floats2half2_rn(r6, r7);
        g_hh[i] = o;
    }
}

// ---------------- launch ----------------
extern "C" void kernel_launch(void* const* d_in, const int* in_sizes, int n_in,
                              void* d_out, int out_size) {
    const float* x    = (const float*)d_in[0];
    const int*   ei   = (const int*)d_in[1];
    const int*   esrc = ei;
    const int*   edst = ei + NE;
    const float* wn0 = (const float*)d_in[2];
    const float* ws0 = (const float*)d_in[3];
    const float* b0  = (const float*)d_in[4];
    const float* g0  = (const float*)d_in[5];
    const float* be0 = (const float*)d_in[6];
    const float* wn1 = (const float*)d_in[7];
    const float* ws1 = (const float*)d_in[8];
    const float* b1  = (const float*)d_in[9];
    const float* g1  = (const float*)d_in[10];
    const float* be1 = (const float*)d_in[11];
    const float* wn2 = (const float*)d_in[12];
    const float* ws2 = (const float*)d_in[13];
    const float* b2  = (const float*)d_in[14];
    const float* g2  = (const float*)d_in[15];
    const float* be2 = (const float*)d_in[16];
    float* out = (float*)d_out;

    const int NBLK = (NN + 1023) / 1024;   // 49

    k_zero_cnt<<<(NN + 255) / 256, 256>>>();
    k_hist<<<(NE + 255) / 256, 256>>>(edst);
    k_scan1<<<NBLK, 1024>>>();
    k_scan23<<<NBLK, 1024>>>();
    k_fill<<<(NE + 255) / 256, 256>>>(esrc, edst);
    k_cvtx<<<(NN * 16 + 255) / 256, 256>>>(x);
    k_cvtw_all<<<dim3(8, 8, 6), dim3(32, 8)>>>(wn0, ws0, wn1, ws1, wn2, ws2);

    const int M_TILES = (NN + 127) / 128;

    // ---- layer 0: 128 -> 256 ----
    k_agg<128, true><<<(NN * 16 + 255) / 256, 256>>>();
    k_gemm<128, 256, true><<<dim3(4, M_TILES), 256>>>(OFF_WN0, OFF_WS0, b0, 0);
    k_bnapply<256, true, false><<<(NN * 32 + 255) / 256, 256>>>(g0, be0, 0, nullptr);

    // ---- layer 1: 256 -> 256 ----
    k_agg<256, false><<<(NN * 32 + 255) / 256, 256>>>();
    k_gemm<256, 256, false><<<dim3(4, M_TILES), 256>>>(OFF_WN1, OFF_WS1, b1, 1);
    k_bnapply<256, true, false><<<(NN * 32 + 255) / 256, 256>>>(g1, be1, 1, nullptr);

    // ---- layer 2: 256 -> 128 ----
    k_agg<256, false><<<(NN * 32 + 255) / 256, 256>>>();
    k_gemm<256, 128, false><<<dim3(2, M_TILES), 256>>>(OFF_WN2, OFF_WS2, b2, 2);
    k_bnapply<128, false, true><<<(NN * 16 + 255) / 256, 256>>>(g2, be2, 2, out);
}

// round 14
// speedup vs baseline: 1.3444x; 1.1617x over previous
#include <cuda_runtime.h>
#include <cuda_fp16.h>
#include <cstdint>

#define NN 50000
#define NE 800000

// ---------------- static device scratch ----------------
__device__ int    g_cnt[NN];
__device__ int    g_fill[NN];
__device__ int    g_rowptr[NN + 1];
__device__ float  g_invdeg[NN];
__device__ int    g_csr[NE];
__device__ int    g_blksum[64];
__device__ uint4  g_xh[(size_t)NN * 16];   // x fp16 (128 cols)
__device__ uint4  g_hh[(size_t)NN * 32];   // hidden activations fp16
__device__ uint4  g_mh[(size_t)NN * 32];   // aggregated mean fp16
__device__ float4 g_pre[(size_t)NN * 64];  // pre-BN linear output fp32
__device__ __half g_wh[262144];            // all 6 weights fp16, [D][K]
__device__ float  g_sum[768];              // 3 layers x 256
__device__ float  g_sumsq[768];

#define OFF_WN0 0
#define OFF_WS0 32768
#define OFF_WN1 65536
#define OFF_WS1 131072
#define OFF_WN2 196608
#define OFF_WS2 229376

#define ASTRIDE 12   // unsigned units; 48B row stride -> every row 16B aligned

// ---------------- helpers ----------------
__device__ __forceinline__ void mma_fp16(float* c, const unsigned* a, const unsigned* b) {
    asm("mma.sync.aligned.m16n8k16.row.col.f32.f16.f16.f32 "
        "{%0,%1,%2,%3}, {%4,%5,%6,%7}, {%8,%9}, {%0,%1,%2,%3};"
        : "+f"(c[0]), "+f"(c[1]), "+f"(c[2]), "+f"(c[3])
        : "r"(a[0]), "r"(a[1]), "r"(a[2]), "r"(a[3]),
          "r"(b[0]), "r"(b[1]));
}
__device__ __forceinline__ void ldsm_x4(unsigned* r, uint32_t addr) {
    asm volatile("ldmatrix.sync.aligned.m8n8.x4.shared.b16 {%0,%1,%2,%3}, [%4];"
        : "=r"(r[0]), "=r"(r[1]), "=r"(r[2]), "=r"(r[3]) : "r"(addr));
}
__device__ __forceinline__ void ldsm_x2(unsigned* r, uint32_t addr) {
    asm volatile("ldmatrix.sync.aligned.m8n8.x2.shared.b16 {%0,%1}, [%2];"
        : "=r"(r[0]), "=r"(r[1]) : "r"(addr));
}
__device__ __forceinline__ void cp_async16(uint32_t dst, const void* src, int src_size) {
    asm volatile("cp.async.cg.shared.global [%0], [%1], 16, %2;"
        :: "r"(dst), "l"(src), "r"(src_size));
}
__device__ __forceinline__ void cp_commit() {
    asm volatile("cp.async.commit_group;");
}
__device__ __forceinline__ void cp_wait0() {
    asm volatile("cp.async.wait_group 0;");
}

// ---------------- CSR build ----------------
__global__ void k_zero_cnt() {
    int i = blockIdx.x * blockDim.x + threadIdx.x;
    if (i < NN) { g_cnt[i] = 0; g_fill[i] = 0; }
    if (i < 768) { g_sum[i] = 0.f; g_sumsq[i] = 0.f; }
}

__global__ void k_hist(const int* __restrict__ dst) {
    int e = blockIdx.x * blockDim.x + threadIdx.x;
    if (e < NE) atomicAdd(&g_cnt[dst[e]], 1);
}

__global__ void k_scan1() {
    __shared__ int wsum[32];
    const int tid  = threadIdx.x;
    const int lane = tid & 31;
    const int wid  = tid >> 5;
    const int i = blockIdx.x * 1024 + tid;
    int v = (i < NN) ? g_cnt[i] : 0;
    int x = v;
    #pragma unroll
    for (int d = 1; d < 32; d <<= 1) {
        int t = __shfl_up_sync(0xffffffffu, x, d);
        if (lane >= d) x += t;
    }
    if (lane == 31) wsum[wid] = x;
    __syncthreads();
    if (wid == 0) {
        int w = wsum[lane];
        #pragma unroll
        for (int d = 1; d < 32; d <<= 1) {
            int t = __shfl_up_sync(0xffffffffu, w, d);
            if (lane >= d) w += t;
        }
        wsum[lane] = w;
    }
    __syncthreads();
    int incl = x + (wid ? wsum[wid - 1] : 0);
    if (i < NN) {
        g_rowptr[i + 1] = incl;
        g_invdeg[i] = 1.0f / (float)max(v, 1);
    }
    if (tid == 1023) g_blksum[blockIdx.x] = incl;
}

__global__ void k_scan23() {
    __shared__ int sv[64];
    const int tid = threadIdx.x;
    const int bid = blockIdx.x;
    if (tid < 64) sv[tid] = (tid < bid) ? g_blksum[tid] : 0;
    __syncthreads();
    if (tid < 32) {
        int v = sv[tid] + sv[tid + 32];
        #pragma unroll
        for (int d = 16; d; d >>= 1) v += __shfl_down_sync(0xffffffffu, v, d);
        if (tid == 0) sv[0] = v;
    }
    __syncthreads();
    const int off = sv[0];
    const int i = bid * 1024 + tid;
    if (i < NN) g_rowptr[i + 1] += off;
    if (i == 0) g_rowptr[0] = 0;
}

__global__ void k_fill(const int* __restrict__ src, const int* __restrict__ dst) {
    int e = blockIdx.x * blockDim.x + threadIdx.x;
    if (e < NE) {
        int d = dst[e];
        int p = g_rowptr[d] + atomicAdd(&g_fill[d], 1);
        g_csr[p] = src[e];
    }
}

// ---------------- x -> fp16 convert ----------------
__global__ void k_cvtx(const float* __restrict__ x) {
    const int total = NN * 16;
    int i = blockIdx.x * blockDim.x + threadIdx.x;
    if (i >= total) return;
    const float4* xp = reinterpret_cast<const float4*>(x);
    float4 a = xp[i * 2], b = xp[i * 2 + 1];
    uint4 o;
    __half2* op = (__half2*)&o;
    op[0] = __floats2half2_rn(a.x, a.y);
    op[1] = __floats2half2_rn(a.z, a.w);
    op[2] = __floats2half2_rn(b.x, b.y);
    op[3] = __floats2half2_rn(b.z, b.w);
    g_xh[i] = o;
}

// ---------------- all 6 weight transposes in one launch ----------------
__global__ void k_cvtw_all(const float* __restrict__ w0, const float* __restrict__ w1,
                           const float* __restrict__ w2, const float* __restrict__ w3,
                           const float* __restrict__ w4, const float* __restrict__ w5) {
    __shared__ float t[32][33];
    const int wi = blockIdx.z;
    const float* w; int K, D, off;
    switch (wi) {
        case 0:  w = w0; K = 128; D = 256; off = OFF_WN0; break;
        case 1:  w = w1; K = 128; D = 256; off = OFF_WS0; break;
        case 2:  w = w2; K = 256; D = 256; off = OFF_WN1; break;
        case 3:  w = w3; K = 256; D = 256; off = OFF_WS1; break;
        case 4:  w = w4; K = 256; D = 128; off = OFF_WN2; break;
        default: w = w5; K = 256; D = 128; off = OFF_WS2; break;
    }
    const int d0 = blockIdx.x * 32, k0 = blockIdx.y * 32;
    if (d0 >= D || k0 >= K) return;
    const int tx = threadIdx.x, ty = threadIdx.y;
    #pragma unroll
    for (int i = ty; i < 32; i += 8)
        t[i][tx] = w[(size_t)(k0 + i) * D + d0 + tx];
    __syncthreads();
    #pragma unroll
    for (int i = ty; i < 32; i += 8)
        g_wh[off + (size_t)(d0 + i) * K + k0 + tx] = __float2half_rn(t[tx][i]);
}

// ---------------- mean aggregation ----------------
template<int DIN, bool FROMX>
__global__ void k_agg() {
    const int TPN = DIN / 8;
    int t = blockIdx.x * blockDim.x + threadIdx.x;
    int node = t / TPN;
    if (node >= NN) return;
    int c8 = t % TPN;
    const uint4* __restrict__ hin = FROMX ? g_xh : g_hh;
    int beg = g_rowptr[node], end = g_rowptr[node + 1];
    float a0 = 0.f, a1 = 0.f, a2 = 0.f, a3 = 0.f;
    float a4 = 0.f, a5 = 0.f, a6 = 0.f, a7 = 0.f;
    for (int e = beg; e < end; e++) {
        int s = g_csr[e];
        uint4 u = hin[(size_t)s * TPN + c8];
        const __half2* hp = (const __half2*)&u;
        float2 f0 = __half22float2(hp[0]);
        float2 f1 = __half22float2(hp[1]);
        float2 f2 = __half22float2(hp[2]);
        float2 f3 = __half22float2(hp[3]);
        a0 += f0.x; a1 += f0.y; a2 += f1.x; a3 += f1.y;
        a4 += f2.x; a5 += f2.y; a6 += f3.x; a7 += f3.y;
    }
    float inv = g_invdeg[node];
    uint4 o;
    __half2* op = (__half2*)&o;
    op[0] = __floats2half2_rn(a0 * inv, a1 * inv);
    op[1] = __floats2half2_rn(a2 * inv, a3 * inv);
    op[2] = __floats2half2_rn(a4 * inv, a5 * inv);
    op[3] = __floats2half2_rn(a6 * inv, a7 * inv);
    g_mh[(size_t)node * TPN + c8] = o;
}

// ---------------- fused dual GEMM (fp16 HMMA, 128x64 tile, ldmatrix, cp.async x2) ----------------
template<int K, int DOUT, bool FROMX>
__global__ __launch_bounds__(256) void k_gemm(
    int off1, int off2, const float* __restrict__ bias, int layer)
{
    __shared__ unsigned As2[2][128 * ASTRIDE];
    __shared__ unsigned Bs2[2][64 * ASTRIDE];

    const int tid    = threadIdx.x;
    const int lane   = tid & 31;
    const int wid    = tid >> 5;
    const int mbase  = (wid >> 1) * 32;
    const int nbase  = (wid & 1) * 32;
    const int n0 = blockIdx.x * 64;
    const int m0 = blockIdx.y * 128;

    const int a_row = tid >> 1;
    const int a_u4  = tid & 1;
    const int b_n   = tid >> 1;
    const int b_u4  = tid & 1;

    const int THK = K / 8;
    const int CPP = K / 16;      // chunks per phase
    const int NCH = 2 * CPP;
    const uint4* A1 = g_mh;
    const uint4* A2 = FROMX ? g_xh : g_hh;
    const __half* B1w = g_wh + off1;
    const __half* B2w = g_wh + off2;
    float*       C  = (float*)g_pre;

    const uint32_t sbA = (uint32_t)__cvta_generic_to_shared(&As2[0][0]);
    const uint32_t sbB = (uint32_t)__cvta_generic_to_shared(&Bs2[0][0]);
    const uint32_t ABYTES = 128u * ASTRIDE * 4u;
    const uint32_t BBYTES = 64u * ASTRIDE * 4u;

    // staging destinations
    const uint32_t dstA = sbA + 4u * (a_row * ASTRIDE + a_u4 * 4);
    const uint32_t dstB = sbB + 4u * (b_n * ASTRIDE + b_u4 * 4);

    // A-row predicate (clamped source; src_size=0 zero-fills smem)
    const int gr   = m0 + a_row;
    const int grc  = (gr < NN) ? gr : 0;
    const int asz  = (gr < NN) ? 16 : 0;

    // ldmatrix source addresses (buffer 0; add buf*bytes at use)
    const int quad = lane >> 3, lr = lane & 7;
    uint32_t addrA[2], addrB[4];
    #pragma unroll
    for (int sm = 0; sm < 2; sm++) {
        int row = mbase + sm * 16 + (quad & 1) * 8 + lr;
        int kp  = (quad >> 1) * 4;
        addrA[sm] = sbA + 4u * (row * ASTRIDE + kp);
    }
    {
        const int l16 = lane & 15;
        #pragma unroll
        for (int sn = 0; sn < 4; sn++) {
            int row = nbase + sn * 8 + (l16 & 7);
            int kp  = (l16 >> 3) * 4;
            addrB[sn] = sbB + 4u * (row * ASTRIDE + kp);
        }
    }

    float acc[2][4][4];
    #pragma unroll
    for (int i = 0; i < 2; i++)
        #pragma unroll
        for (int j = 0; j < 4; j++)
            #pragma unroll
            for (int r = 0; r < 4; r++) acc[i][j][r] = 0.f;

    // stage chunk c into buffer b
    auto stage = [&](int c, int b) {
        const int phase = (c >= CPP);
        const int k0    = (c - phase * CPP) * 16;
        const uint4*  A = phase ? A2 : A1;
        const __half* B = phase ? B2w : B1w;
        cp_async16(dstA + b * ABYTES,
                   A + (size_t)grc * THK + (k0 >> 3) + a_u4, asz);
        if (b_n < 64)
            cp_async16(dstB + b * BBYTES,
                       B + (size_t)(n0 + b_n) * K + k0 + b_u4 * 8, 16);
        cp_commit();
    };

    stage(0, 0);
    cp_wait0();
    __syncthreads();

    for (int c = 0; c < NCH; c++) {
        const int buf = c & 1;
        if (c + 1 < NCH) stage(c + 1, buf ^ 1);

        const uint32_t oA = buf * ABYTES;
        const uint32_t oB = buf * BBYTES;
        unsigned af[2][4];
        ldsm_x4(af[0], addrA[0] + oA);
        ldsm_x4(af[1], addrA[1] + oA);
        #pragma unroll
        for (int sn = 0; sn < 4; sn++) {
            unsigned bf[2];
            ldsm_x2(bf, addrB[sn] + oB);
            mma_fp16(acc[0][sn], af[0], bf);
            mma_fp16(acc[1][sn], af[1], bf);
        }

        if (c + 1 < NCH) {
            cp_wait0();
            __syncthreads();
        }
    }

    // ---------------- epilogue: bias + store + BN partials ----------------
    #pragma unroll
    for (int sn = 0; sn < 4; sn++) {
        const int colg = n0 + nbase + sn * 8 + 2 * (lane & 3);
        const float bb0 = bias[colg];
        const float bb1 = bias[colg + 1];
        float s0 = 0.f, s1 = 0.f, q0 = 0.f, q1 = 0.f;
        #pragma unroll
        for (int sm = 0; sm < 2; sm++) {
            const int r0 = m0 + mbase + sm * 16 + (lane >> 2);
            const int r1 = r0 + 8;
            float v0 = acc[sm][sn][0] + bb0;
            float v1 = acc[sm][sn][1] + bb1;
            float v2 = acc[sm][sn][2] + bb0;
            float v3 = acc[sm][sn][3] + bb1;
            if (r0 < NN) {
                *reinterpret_cast<float2*>(C + (size_t)r0 * DOUT + colg) =
                    make_float2(v0, v1);
                s0 += v0; q0 += v0 * v0;
                s1 += v1; q1 += v1 * v1;
            }
            if (r1 < NN) {
                *reinterpret_cast<float2*>(C + (size_t)r1 * DOUT + colg) =
                    make_float2(v2, v3);
                s0 += v2; q0 += v2 * v2;
                s1 += v3; q1 += v3 * v3;
            }
        }
        #pragma unroll
        for (int d = 16; d >= 4; d >>= 1) {
            s0 += __shfl_down_sync(0xffffffffu, s0, d);
            s1 += __shfl_down_sync(0xffffffffu, s1, d);
            q0 += __shfl_down_sync(0xffffffffu, q0, d);
            q1 += __shfl_down_sync(0xffffffffu, q1, d);
        }
        if (lane < 4) {
            const int cg = n0 + nbase + sn * 8 + 2 * lane;
            atomicAdd(&g_sum  [layer * 256 + cg],     s0);
            atomicAdd(&g_sum  [layer * 256 + cg + 1], s1);
            atomicAdd(&g_sumsq[layer * 256 + cg],     q0);
            atomicAdd(&g_sumsq[layer * 256 + cg + 1], q1);
        }
    }
}

// ---------------- BN finalize (in-block) + apply ----------------
template<int DOUT, bool RELU, bool TOOUT>
__global__ __launch_bounds__(256) void k_bnapply(
    const float* __restrict__ gamma, const float* __restrict__ beta,
    int layer, float* __restrict__ outp)
{
    __shared__ float s_scale[DOUT], s_shift[DOUT];
    const int tid = threadIdx.x;
    if (tid < DOUT) {
        float mu  = g_sum[layer * 256 + tid] * (1.0f / NN);
        float var = g_sumsq[layer * 256 + tid] * (1.0f / NN) - mu * mu;
        float sc  = gamma[tid] * rsqrtf(var + 1e-5f);
        s_scale[tid] = sc;
        s_shift[tid] = beta[tid] - mu * sc;
    }
    __syncthreads();

    const int total = NN * (DOUT / 8);
    int i = blockIdx.x * blockDim.x + tid;
    if (i >= total) return;
    int c8 = (i % (DOUT / 8)) * 8;
    float4 v0 = g_pre[i * 2];
    float4 v1 = g_pre[i * 2 + 1];
    float r0 = v0.x * s_scale[c8 + 0] + s_shift[c8 + 0];
    float r1 = v0.y * s_scale[c8 + 1] + s_shift[c8 + 1];
    float r2 = v0.z * s_scale[c8 + 2] + s_shift[c8 + 2];
    float r3 = v0.w * s_scale[c8 + 3] + s_shift[c8 + 3];
    float r4 = v1.x * s_scale[c8 + 4] + s_shift[c8 + 4];
    float r5 = v1.y * s_scale[c8 + 5] + s_shift[c8 + 5];
    float r6 = v1.z * s_scale[c8 + 6] + s_shift[c8 + 6];
    float r7 = v1.w * s_scale[c8 + 7] + s_shift[c8 + 7];
    if (RELU) {
        r0 = fmaxf(r0, 0.f); r1 = fmaxf(r1, 0.f);
        r2 = fmaxf(r2, 0.f); r3 = fmaxf(r3, 0.f);
        r4 = fmaxf(r4, 0.f); r5 = fmaxf(r5, 0.f);
        r6 = fmaxf(r6, 0.f); r7 = fmaxf(r7, 0.f);
    }
    if (TOOUT) {
        float4* op = reinterpret_cast<float4*>(outp);
        op[i * 2]     = make_float4(r0, r1, r2, r3);
        op[i * 2 + 1] = make_float4(r4, r5, r6, r7);
    } else {
        uint4 o;
        __half2* hp = (__half2*)&o;
        hp[0] = __floats2half2_rn(r0, r1);
        hp[1] = __floats2half2_rn(r2, r3);
        hp[2] = __floats2half2_rn(r4, r5);
        hp[3] = __floats2half2_rn(r6, r7);
        g_hh[i] = o;
    }
}

// ---------------- launch ----------------
extern "C" void kernel_launch(void* const* d_in, const int* in_sizes, int n_in,
                              void* d_out, int out_size) {
    const float* x    = (const float*)d_in[0];
    const int*   ei   = (const int*)d_in[1];
    const int*   esrc = ei;
    const int*   edst = ei + NE;
    const float* wn0 = (const float*)d_in[2];
    const float* ws0 = (const float*)d_in[3];
    const float* b0  = (const float*)d_in[4];
    const float* g0  = (const float*)d_in[5];
    const float* be0 = (const float*)d_in[6];
    const float* wn1 = (const float*)d_in[7];
    const float* ws1 = (const float*)d_in[8];
    const float* b1  = (const float*)d_in[9];
    const float* g1  = (const float*)d_in[10];
    const float* be1 = (const float*)d_in[11];
    const float* wn2 = (const float*)d_in[12];
    const float* ws2 = (const float*)d_in[13];
    const float* b2  = (const float*)d_in[14];
    const float* g2  = (const float*)d_in[15];
    const float* be2 = (const float*)d_in[16];
    float* out = (float*)d_out;

    const int NBLK = (NN + 1023) / 1024;   // 49

    k_zero_cnt<<<(NN + 255) / 256, 256>>>();
    k_hist<<<(NE + 255) / 256, 256>>>(edst);
    k_scan1<<<NBLK, 1024>>>();
    k_scan23<<<NBLK, 1024>>>();
    k_fill<<<(NE + 255) / 256, 256>>>(esrc, edst);
    k_cvtx<<<(NN * 16 + 255) / 256, 256>>>(x);
    k_cvtw_all<<<dim3(8, 8, 6), dim3(32, 8)>>>(wn0, ws0, wn1, ws1, wn2, ws2);

    const int M_TILES = (NN + 127) / 128;

    // ---- layer 0: 128 -> 256 ----
    k_agg<128, true><<<(NN * 16 + 255) / 256, 256>>>();
    k_gemm<128, 256, true><<<dim3(4, M_TILES), 256>>>(OFF_WN0, OFF_WS0, b0, 0);
    k_bnapply<256, true, false><<<(NN * 32 + 255) / 256, 256>>>(g0, be0, 0, nullptr);

    // ---- layer 1: 256 -> 256 ----
    k_agg<256, false><<<(NN * 32 + 255) / 256, 256>>>();
    k_gemm<256, 256, false><<<dim3(4, M_TILES), 256>>>(OFF_WN1, OFF_WS1, b1, 1);
    k_bnapply<256, true, false><<<(NN * 32 + 255) / 256, 256>>>(g1, be1, 1, nullptr);

    // ---- layer 2: 256 -> 128 ----
    k_agg<256, false><<<(NN * 32 + 255) / 256, 256>>>();
    k_gemm<256, 128, false><<<dim3(2, M_TILES), 256>>>(OFF_WN2, OFF_WS2, b2, 2);
    k_bnapply<128, false, true><<<(NN * 16 + 255) / 256, 256>>>(g2, be2, 2, out);
}

// round 15
// speedup vs baseline: 1.3994x; 1.0410x over previous
#include <cuda_runtime.h>
#include <cuda_fp16.h>
#include <cstdint>

#define NN 50000
#define NE 800000

// ---------------- static device scratch ----------------
__device__ int    g_cnt[NN];
__device__ int    g_fill[NN];
__device__ int    g_rowptr[NN + 1];
__device__ float  g_invdeg[NN];
__device__ int    g_csr[NE];
__device__ int    g_blksum[64];
__device__ uint4  g_xh[(size_t)NN * 16];   // x fp16 (128 cols)
__device__ uint4  g_hh[(size_t)NN * 32];   // hidden activations fp16
__device__ uint4  g_mh[(size_t)NN * 32];   // aggregated mean fp16
__device__ float4 g_pre[(size_t)NN * 64];  // pre-BN output: fp32 (layer2) or fp16 (layers 0/1)
__device__ __half g_wh[262144];            // all 6 weights fp16, [D][K]
__device__ float  g_sum[768];              // 3 layers x 256
__device__ float  g_sumsq[768];

#define OFF_WN0 0
#define OFF_WS0 32768
#define OFF_WN1 65536
#define OFF_WS1 131072
#define OFF_WN2 196608
#define OFF_WS2 229376

#define AST 20   // unsigned units per smem row (80B): 16B-aligned rows, ldmatrix conflict-free

// ---------------- helpers ----------------
__device__ __forceinline__ void mma_fp16(float* c, const unsigned* a, const unsigned* b) {
    asm("mma.sync.aligned.m16n8k16.row.col.f32.f16.f16.f32 "
        "{%0,%1,%2,%3}, {%4,%5,%6,%7}, {%8,%9}, {%0,%1,%2,%3};"
        : "+f"(c[0]), "+f"(c[1]), "+f"(c[2]), "+f"(c[3])
        : "r"(a[0]), "r"(a[1]), "r"(a[2]), "r"(a[3]),
          "r"(b[0]), "r"(b[1]));
}
__device__ __forceinline__ void ldsm_x4(unsigned* r, uint32_t addr) {
    asm volatile("ldmatrix.sync.aligned.m8n8.x4.shared.b16 {%0,%1,%2,%3}, [%4];"
        : "=r"(r[0]), "=r"(r[1]), "=r"(r[2]), "=r"(r[3]) : "r"(addr));
}
__device__ __forceinline__ void ldsm_x2(unsigned* r, uint32_t addr) {
    asm volatile("ldmatrix.sync.aligned.m8n8.x2.shared.b16 {%0,%1}, [%2];"
        : "=r"(r[0]), "=r"(r[1]) : "r"(addr));
}
__device__ __forceinline__ void cp_async16(uint32_t dst, const void* src, int src_size) {
    asm volatile("cp.async.cg.shared.global [%0], [%1], 16, %2;"
        :: "r"(dst), "l"(src), "r"(src_size));
}
__device__ __forceinline__ void cp_commit() {
    asm volatile("cp.async.commit_group;");
}
__device__ __forceinline__ void cp_wait0() {
    asm volatile("cp.async.wait_group 0;");
}

// ---------------- CSR build ----------------
__global__ void k_zero_cnt() {
    int i = blockIdx.x * blockDim.x + threadIdx.x;
    if (i < NN) { g_cnt[i] = 0; g_fill[i] = 0; }
    if (i < 768) { g_sum[i] = 0.f; g_sumsq[i] = 0.f; }
}

__global__ void k_hist(const int* __restrict__ dst) {
    int e = blockIdx.x * blockDim.x + threadIdx.x;
    if (e < NE) atomicAdd(&g_cnt[dst[e]], 1);
}

__global__ void k_scan1() {
    __shared__ int wsum[32];
    const int tid  = threadIdx.x;
    const int lane = tid & 31;
    const int wid  = tid >> 5;
    const int i = blockIdx.x * 1024 + tid;
    int v = (i < NN) ? g_cnt[i] : 0;
    int x = v;
    #pragma unroll
    for (int d = 1; d < 32; d <<= 1) {
        int t = __shfl_up_sync(0xffffffffu, x, d);
        if (lane >= d) x += t;
    }
    if (lane == 31) wsum[wid] = x;
    __syncthreads();
    if (wid == 0) {
        int w = wsum[lane];
        #pragma unroll
        for (int d = 1; d < 32; d <<= 1) {
            int t = __shfl_up_sync(0xffffffffu, w, d);
            if (lane >= d) w += t;
        }
        wsum[lane] = w;
    }
    __syncthreads();
    int incl = x + (wid ? wsum[wid - 1] : 0);
    if (i < NN) {
        g_rowptr[i + 1] = incl;
        g_invdeg[i] = 1.0f / (float)max(v, 1);
    }
    if (tid == 1023) g_blksum[blockIdx.x] = incl;
}

__global__ void k_scan23() {
    __shared__ int sv[64];
    const int tid = threadIdx.x;
    const int bid = blockIdx.x;
    if (tid < 64) sv[tid] = (tid < bid) ? g_blksum[tid] : 0;
    __syncthreads();
    if (tid < 32) {
        int v = sv[tid] + sv[tid + 32];
        #pragma unroll
        for (int d = 16; d; d >>= 1) v += __shfl_down_sync(0xffffffffu, v, d);
        if (tid == 0) sv[0] = v;
    }
    __syncthreads();
    const int off = sv[0];
    const int i = bid * 1024 + tid;
    if (i < NN) g_rowptr[i + 1] += off;
    if (i == 0) g_rowptr[0] = 0;
}

__global__ void k_fill(const int* __restrict__ src, const int* __restrict__ dst) {
    int e = blockIdx.x * blockDim.x + threadIdx.x;
    if (e < NE) {
        int d = dst[e];
        int p = g_rowptr[d] + atomicAdd(&g_fill[d], 1);
        g_csr[p] = src[e];
    }
}

// ---------------- x -> fp16 convert ----------------
__global__ void k_cvtx(const float* __restrict__ x) {
    const int total = NN * 16;
    int i = blockIdx.x * blockDim.x + threadIdx.x;
    if (i >= total) return;
    const float4* xp = reinterpret_cast<const float4*>(x);
    float4 a = xp[i * 2], b = xp[i * 2 + 1];
    uint4 o;
    __half2* op = (__half2*)&o;
    op[0] = __floats2half2_rn(a.x, a.y);
    op[1] = __floats2half2_rn(a.z, a.w);
    op[2] = __floats2half2_rn(b.x, b.y);
    op[3] = __floats2half2_rn(b.z, b.w);
    g_xh[i] = o;
}

// ---------------- all 6 weight transposes in one launch ----------------
__global__ void k_cvtw_all(const float* __restrict__ w0, const float* __restrict__ w1,
                           const float* __restrict__ w2, const float* __restrict__ w3,
                           const float* __restrict__ w4, const float* __restrict__ w5) {
    __shared__ float t[32][33];
    const int wi = blockIdx.z;
    const float* w; int K, D, off;
    switch (wi) {
        case 0:  w = w0; K = 128; D = 256; off = OFF_WN0; break;
        case 1:  w = w1; K = 128; D = 256; off = OFF_WS0; break;
        case 2:  w = w2; K = 256; D = 256; off = OFF_WN1; break;
        case 3:  w = w3; K = 256; D = 256; off = OFF_WS1; break;
        case 4:  w = w4; K = 256; D = 128; off = OFF_WN2; break;
        default: w = w5; K = 256; D = 128; off = OFF_WS2; break;
    }
    const int d0 = blockIdx.x * 32, k0 = blockIdx.y * 32;
    if (d0 >= D || k0 >= K) return;
    const int tx = threadIdx.x, ty = threadIdx.y;
    #pragma unroll
    for (int i = ty; i < 32; i += 8)
        t[i][tx] = w[(size_t)(k0 + i) * D + d0 + tx];
    __syncthreads();
    #pragma unroll
    for (int i = ty; i < 32; i += 8)
        g_wh[off + (size_t)(d0 + i) * K + k0 + tx] = __float2half_rn(t[tx][i]);
}

// ---------------- mean aggregation ----------------
template<int DIN, bool FROMX>
__global__ void k_agg() {
    const int TPN = DIN / 8;
    int t = blockIdx.x * blockDim.x + threadIdx.x;
    int node = t / TPN;
    if (node >= NN) return;
    int c8 = t % TPN;
    const uint4* __restrict__ hin = FROMX ? g_xh : g_hh;
    int beg = g_rowptr[node], end = g_rowptr[node + 1];
    float a0 = 0.f, a1 = 0.f, a2 = 0.f, a3 = 0.f;
    float a4 = 0.f, a5 = 0.f, a6 = 0.f, a7 = 0.f;
    for (int e = beg; e < end; e++) {
        int s = g_csr[e];
        uint4 u = hin[(size_t)s * TPN + c8];
        const __half2* hp = (const __half2*)&u;
        float2 f0 = __half22float2(hp[0]);
        float2 f1 = __half22float2(hp[1]);
        float2 f2 = __half22float2(hp[2]);
        float2 f3 = __half22float2(hp[3]);
        a0 += f0.x; a1 += f0.y; a2 += f1.x; a3 += f1.y;
        a4 += f2.x; a5 += f2.y; a6 += f3.x; a7 += f3.y;
    }
    float inv = g_invdeg[node];
    uint4 o;
    __half2* op = (__half2*)&o;
    op[0] = __floats2half2_rn(a0 * inv, a1 * inv);
    op[1] = __floats2half2_rn(a2 * inv, a3 * inv);
    op[2] = __floats2half2_rn(a4 * inv, a5 * inv);
    op[3] = __floats2half2_rn(a6 * inv, a7 * inv);
    g_mh[(size_t)node * TPN + c8] = o;
}

// ---------------- fused dual GEMM: 128x64 tile, 32-wide K chunks, cp.async x2 ----------------
// HALFPRE: store pre-activations as fp16 (layers 0/1); else fp32 (layer 2).
template<int K, int DOUT, bool FROMX, bool HALFPRE>
__global__ __launch_bounds__(256) void k_gemm(
    int off1, int off2, const float* __restrict__ bias, int layer)
{
    __shared__ unsigned As2[2][128 * AST];
    __shared__ unsigned Bs2[2][64 * AST];

    const int tid    = threadIdx.x;
    const int lane   = tid & 31;
    const int wid    = tid >> 5;
    const int mbase  = (wid >> 1) * 32;
    const int nbase  = (wid & 1) * 32;
    const int n0 = blockIdx.x * 64;
    const int m0 = blockIdx.y * 128;

    const int a_row = tid >> 1;         // 0..127
    const int a_g   = tid & 1;          // stages 16B groups {a_g, a_g+2} of 4
    const int b_n   = tid >> 2;         // 0..63
    const int b_g   = tid & 3;          // one 16B group of 4

    const int THK = K / 8;
    const int CPP = K / 32;             // 32-wide chunks per phase
    const int NCH = 2 * CPP;
    const uint4* A1 = g_mh;
    const uint4* A2 = FROMX ? g_xh : g_hh;
    const __half* B1w = g_wh + off1;
    const __half* B2w = g_wh + off2;

    const uint32_t sbA = (uint32_t)__cvta_generic_to_shared(&As2[0][0]);
    const uint32_t sbB = (uint32_t)__cvta_generic_to_shared(&Bs2[0][0]);
    const uint32_t ABYTES = 128u * AST * 4u;
    const uint32_t BBYTES = 64u * AST * 4u;

    const uint32_t dstA0 = sbA + 4u * (a_row * AST + a_g * 4);
    const uint32_t dstA1 = dstA0 + 32u;        // group a_g+2
    const uint32_t dstB  = sbB + 4u * (b_n * AST + b_g * 4);

    const int gr   = m0 + a_row;
    const int grc  = (gr < NN) ? gr : 0;
    const int asz  = (gr < NN) ? 16 : 0;

    // ldmatrix addresses (buffer 0, k16-half 0)
    const int quad = lane >> 3, lr = lane & 7;
    uint32_t addrA[2], addrB[4];
    #pragma unroll
    for (int sm = 0; sm < 2; sm++) {
        int row = mbase + sm * 16 + (quad & 1) * 8 + lr;
        int kp  = (quad >> 1) * 4;
        addrA[sm] = sbA + 4u * (row * AST + kp);
    }
    {
        const int l16 = lane & 15;
        #pragma unroll
        for (int sn = 0; sn < 4; sn++) {
            int row = nbase + sn * 8 + (l16 & 7);
            int kp  = (l16 >> 3) * 4;
            addrB[sn] = sbB + 4u * (row * AST + kp);
        }
    }

    float acc[2][4][4];
    #pragma unroll
    for (int i = 0; i < 2; i++)
        #pragma unroll
        for (int j = 0; j < 4; j++)
            #pragma unroll
            for (int r = 0; r < 4; r++) acc[i][j][r] = 0.f;

    auto stage = [&](int c, int b) {
        const int phase = (c >= CPP);
        const int k0    = (c - phase * CPP) * 32;
        const uint4*  A = phase ? A2 : A1;
        const __half* B = phase ? B2w : B1w;
        const uint4* as = A + (size_t)grc * THK + (k0 >> 3);
        cp_async16(dstA0 + b * ABYTES, as + a_g,     asz);
        cp_async16(dstA1 + b * ABYTES, as + a_g + 2, asz);
        cp_async16(dstB  + b * BBYTES,
                   B + (size_t)(n0 + b_n) * K + k0 + b_g * 8, 16);
        cp_commit();
    };

    stage(0, 0);
    cp_wait0();
    __syncthreads();

    for (int c = 0; c < NCH; c++) {
        const int buf = c & 1;
        if (c + 1 < NCH) stage(c + 1, buf ^ 1);

        const uint32_t oA = buf * ABYTES;
        const uint32_t oB = buf * BBYTES;
        #pragma unroll
        for (int h = 0; h < 2; h++) {
            const uint32_t hk = h * 32u;   // +8 unsigned = second k16 half
            unsigned af[2][4];
            ldsm_x4(af[0], addrA[0] + oA + hk);
            ldsm_x4(af[1], addrA[1] + oA + hk);
            #pragma unroll
            for (int sn = 0; sn < 4; sn++) {
                unsigned bf[2];
                ldsm_x2(bf, addrB[sn] + oB + hk);
                mma_fp16(acc[0][sn], af[0], bf);
                mma_fp16(acc[1][sn], af[1], bf);
            }
        }

        if (c + 1 < NCH) {
            cp_wait0();
            __syncthreads();
        }
    }

    // ---------------- epilogue: bias + store + BN partials ----------------
    float*  Cf = (float*)g_pre;
    __half* Ch = (__half*)g_pre;

    #pragma unroll
    for (int sn = 0; sn < 4; sn++) {
        const int colg = n0 + nbase + sn * 8 + 2 * (lane & 3);
        const float bb0 = bias[colg];
        const float bb1 = bias[colg + 1];
        float s0 = 0.f, s1 = 0.f, q0 = 0.f, q1 = 0.f;
        #pragma unroll
        for (int sm = 0; sm < 2; sm++) {
            const int r0 = m0 + mbase + sm * 16 + (lane >> 2);
            const int r1 = r0 + 8;
            float v0 = acc[sm][sn][0] + bb0;
            float v1 = acc[sm][sn][1] + bb1;
            float v2 = acc[sm][sn][2] + bb0;
            float v3 = acc[sm][sn][3] + bb1;
            if (r0 < NN) {
                if (HALFPRE)
                    *reinterpret_cast<__half2*>(Ch + (size_t)r0 * DOUT + colg) =
                        __floats2half2_rn(v0, v1);
                else
                    *reinterpret_cast<float2*>(Cf + (size_t)r0 * DOUT + colg) =
                        make_float2(v0, v1);
                s0 += v0; q0 += v0 * v0;
                s1 += v1; q1 += v1 * v1;
            }
            if (r1 < NN) {
                if (HALFPRE)
                    *reinterpret_cast<__half2*>(Ch + (size_t)r1 * DOUT + colg) =
                        __floats2half2_rn(v2, v3);
                else
                    *reinterpret_cast<float2*>(Cf + (size_t)r1 * DOUT + colg) =
                        make_float2(v2, v3);
                s0 += v2; q0 += v2 * v2;
                s1 += v3; q1 += v3 * v3;
            }
        }
        #pragma unroll
        for (int d = 16; d >= 4; d >>= 1) {
            s0 += __shfl_down_sync(0xffffffffu, s0, d);
            s1 += __shfl_down_sync(0xffffffffu, s1, d);
            q0 += __shfl_down_sync(0xffffffffu, q0, d);
            q1 += __shfl_down_sync(0xffffffffu, q1, d);
        }
        if (lane < 4) {
            const int cg = n0 + nbase + sn * 8 + 2 * lane;
            atomicAdd(&g_sum  [layer * 256 + cg],     s0);
            atomicAdd(&g_sum  [layer * 256 + cg + 1], s1);
            atomicAdd(&g_sumsq[layer * 256 + cg],     q0);
            atomicAdd(&g_sumsq[layer * 256 + cg + 1], q1);
        }
    }
}

// ---------------- BN finalize (in-block) + apply ----------------
// HALFIN: pre stored as fp16 (layers 0/1); else fp32 (layer 2).
template<int DOUT, bool RELU, bool TOOUT, bool HALFIN>
__global__ __launch_bounds__(256) void k_bnapply(
    const float* __restrict__ gamma, const float* __restrict__ beta,
    int layer, float* __restrict__ outp)
{
    __shared__ float s_scale[DOUT], s_shift[DOUT];
    const int tid = threadIdx.x;
    if (tid < DOUT) {
        float mu  = g_sum[layer * 256 + tid] * (1.0f / NN);
        float var = g_sumsq[layer * 256 + tid] * (1.0f / NN) - mu * mu;
        float sc  = gamma[tid] * rsqrtf(var + 1e-5f);
        s_scale[tid] = sc;
        s_shift[tid] = beta[tid] - mu * sc;
    }
    __syncthreads();

    const int total = NN * (DOUT / 8);
    int i = blockIdx.x * blockDim.x + tid;
    if (i >= total) return;
    int c8 = (i % (DOUT / 8)) * 8;
    float p[8];
    if (HALFIN) {
        uint4 u = reinterpret_cast<const uint4*>(g_pre)[i];
        const __half2* hp = (const __half2*)&u;
        float2 f0 = __half22float2(hp[0]);
        float2 f1 = __half22float2(hp[1]);
        float2 f2 = __half22float2(hp[2]);
        float2 f3 = __half22float2(hp[3]);
        p[0] = f0.x; p[1] = f0.y; p[2] = f1.x; p[3] = f1.y;
        p[4] = f2.x; p[5] = f2.y; p[6] = f3.x; p[7] = f3.y;
    } else {
        float4 v0 = g_pre[i * 2];
        float4 v1 = g_pre[i * 2 + 1];
        p[0] = v0.x; p[1] = v0.y; p[2] = v0.z; p[3] = v0.w;
        p[4] = v1.x; p[5] = v1.y; p[6] = v1.z; p[7] = v1.w;
    }
    float r[8];
    #pragma unroll
    for (int j = 0; j < 8; j++) {
        r[j] = p[j] * s_scale[c8 + j] + s_shift[c8 + j];
        if (RELU) r[j] = fmaxf(r[j], 0.f);
    }
    if (TOOUT) {
        float4* op = reinterpret_cast<float4*>(outp);
        op[i * 2]     = make_float4(r[0], r[1], r[2], r[3]);
        op[i * 2 + 1] = make_float4(r[4], r[5], r[6], r[7]);
    } else {
        uint4 o;
        __half2* hp = (__half2*)&o;
        hp[0] = __floats2half2_rn(r[0], r[1]);
        hp[1] = __floats2half2_rn(r[2], r[3]);
        hp[2] = __floats2half2_rn(r[4], r[5]);
        hp[3] = __floats2half2_rn(r[6], r[7]);
        g_hh[i] = o;
    }
}

// ---------------- launch ----------------
extern "C" void kernel_launch(void* const* d_in, const int* in_sizes, int n_in,
                              void* d_out, int out_size) {
    const float* x    = (const float*)d_in[0];
    const int*   ei   = (const int*)d_in[1];
    const int*   esrc = ei;
    const int*   edst = ei + NE;
    const float* wn0 = (const float*)d_in[2];
    const float* ws0 = (const float*)d_in[3];
    const float* b0  = (const float*)d_in[4];
    const float* g0  = (const float*)d_in[5];
    const float* be0 = (const float*)d_in[6];
    const float* wn1 = (const float*)d_in[7];
    const float* ws1 = (const float*)d_in[8];
    const float* b1  = (const float*)d_in[9];
    const float* g1  = (const float*)d_in[10];
    const float* be1 = (const float*)d_in[11];
    const float* wn2 = (const float*)d_in[12];
    const float* ws2 = (const float*)d_in[13];
    const float* b2  = (const float*)d_in[14];
    const float* g2  = (const float*)d_in[15];
    const float* be2 = (const float*)d_in[16];
    float* out = (float*)d_out;

    const int NBLK = (NN + 1023) / 1024;   // 49

    k_zero_cnt<<<(NN + 255) / 256, 256>>>();
    k_hist<<<(NE + 255) / 256, 256>>>(edst);
    k_scan1<<<NBLK, 1024>>>();
    k_scan23<<<NBLK, 1024>>>();
    k_fill<<<(NE + 255) / 256, 256>>>(esrc, edst);
    k_cvtx<<<(NN * 16 + 255) / 256, 256>>>(x);
    k_cvtw_all<<<dim3(8, 8, 6), dim3(32, 8)>>>(wn0, ws0, wn1, ws1, wn2, ws2);

    const int M_TILES = (NN + 127) / 128;

    // ---- layer 0: 128 -> 256 (fp16 pre) ----
    k_agg<128, true><<<(NN * 16 + 255) / 256, 256>>>();
    k_gemm<128, 256, true, true><<<dim3(4, M_TILES), 256>>>(OFF_WN0, OFF_WS0, b0, 0);
    k_bnapply<256, true, false, true><<<(NN * 32 + 255) / 256, 256>>>(g0, be0, 0, nullptr);

    // ---- layer 1: 256 -> 256 (fp16 pre) ----
    k_agg<256, false><<<(NN * 32 + 255) / 256, 256>>>();
    k_gemm<256, 256, false, true><<<dim3(4, M_TILES), 256>>>(OFF_WN1, OFF_WS1, b1, 1);
    k_bnapply<256, true, false, true><<<(NN * 32 + 255) / 256, 256>>>(g1, be1, 1, nullptr);

    // ---- layer 2: 256 -> 128 (fp32 pre, fp32 out) ----
    k_agg<256, false><<<(NN * 32 + 255) / 256, 256>>>();
    k_gemm<256, 128, false, false><<<dim3(2, M_TILES), 256>>>(OFF_WN2, OFF_WS2, b2, 2);
    k_bnapply<128, false, true, false><<<(NN * 16 + 255) / 256, 256>>>(g2, be2, 2, out);
}